// round 9
// baseline (speedup 1.0000x reference)
#include <cuda_runtime.h>

#define B_    2048
#define FS_   32
#define FA_   16
#define T_    512
#define H_    64
#define SQRT_DT_ 0.22360679774997896f
#define MIN_V_  (-5.0f)
#define MAX_V_  (5.0f)

typedef unsigned long long u64;

__device__ __forceinline__ u64 pack2(float lo, float hi) {
    u64 r; asm("mov.b64 %0, {%1, %2};" : "=l"(r) : "f"(lo), "f"(hi)); return r;
}
__device__ __forceinline__ float2 unpack2(u64 v) {
    float2 f; asm("mov.b64 {%0, %1}, %2;" : "=f"(f.x), "=f"(f.y) : "l"(v)); return f;
}
// packed dual fp32 FMA (sm_100+)
__device__ __forceinline__ u64 ffma2(u64 a, u64 b, u64 c) {
    u64 d; asm("fma.rn.f32x2 %0, %1, %2, %3;" : "=l"(d) : "l"(a), "l"(b), "l"(c)); return d;
}
// accurate tanh from ex2.approx + rcp.approx (~1e-7 abs err)
__device__ __forceinline__ float tanh_acc(float x) {
    float e, r;
    asm("ex2.approx.f32 %0, %1;" : "=f"(e) : "f"(x * 2.8853900817779268f)); // 2*log2(e)
    asm("rcp.approx.f32 %0, %1;" : "=f"(r) : "f"(e + 1.0f));
    return (e - 1.0f) * r;
}

// J-split, occupancy-2 build. Block = 256 threads = 2 groups x 4 warps;
// each group owns 4 batch elements (8/block, grid=256, 2 blocks/SM ->
// 4 warps/SMSP from INDEPENDENT CTAs). Warp (mlp m, j-half jh) holds 80
// weight regs: W1[:, jh*32+lane] (48) + W2[jh*32+k, lane] (32); its L2
// k-range equals its own j-half so L2 consumes only self-produced h ->
// one group barrier per step. Roles 2,3 pre-scale their L2 partials by
// eps*sqrt(dt); exchange is a packed float4 so finalize = 1 LDS.128/el.
__global__ void __launch_bounds__(256, 2)
sde_kernel(const float* __restrict__ a_in,   // (B, FA, T)
           const float* __restrict__ x0,     // (B, FS)
           const float* __restrict__ noise,  // (T-1, B, FS)
           const float* __restrict__ Wf1, const float* __restrict__ bf1,
           const float* __restrict__ Wf2, const float* __restrict__ bf2,
           const float* __restrict__ Wg1, const float* __restrict__ bg1,
           const float* __restrict__ Wg2, const float* __restrict__ bg2,
           float* __restrict__ out)          // (B, FS, T)
{
    const int tid  = threadIdx.x;
    const int wid  = tid >> 5;
    const int lane = tid & 31;
    const int grp  = wid >> 2;            // 0..1
    const int role = wid & 3;             // 0=(f,j0) 1=(f,j1) 2=(g,j0) 3=(g,j1)
    const int jb   = (role & 1) * 32;     // j-half base (= L2 k-half base)
    const bool isg = (role >> 1) != 0;
    const int el0  = grp * 4;
    const int gb0  = blockIdx.x * 8 + el0;

    __shared__ __align__(16) float  v_sm[8][4][32];     // per-warp x / h-half (4KB)
    __shared__ __align__(16) float  a_sg[2][8][4][16];  // a tiles, 4 steps, transposed (4KB)
    __shared__ __align__(16) float4 ex_sm[2][2][4][32]; // [tb][grp][e][lane] packed partials (8KB)

    const float* W1 = isg ? Wg1 : Wf1;
    const float* B1 = isg ? bg1 : bf1;
    const float* W2 = isg ? Wg2 : Wf2;

    // ---- register-resident weight halves (80 regs) ----
    u64 w1h[24];   // W1[k][jb+lane], paired over 48 inputs
#pragma unroll
    for (int kp = 0; kp < 24; kp++)
        w1h[kp] = pack2(W1[(2*kp)*H_ + jb + lane], W1[(2*kp+1)*H_ + jb + lane]);
    u64 w2h[16];   // W2[jb+k][lane], paired over own 32-k half
#pragma unroll
    for (int kp = 0; kp < 16; kp++)
        w2h[kp] = pack2(W2[(jb + 2*kp)*FS_ + lane], W2[(jb + 2*kp + 1)*FS_ + lane]);

    const float b1v   = B1[jb + lane];
    // L2 bias folded into one partial per MLP (added BEFORE the eps scaling
    // for g -- algebraically exact since (p2+bg2)*es + p3*es = (p2+p3+bg2)*es)
    const float pbias = (role == 0) ? bf2[lane] : ((role == 2) ? bg2[lane] : 0.0f);

    const float* a_base  = a_in  + (size_t)gb0 * (FA_*T_) + (size_t)(lane >> 1) * T_ + (lane & 1) * 2;
    const float* nz_base = noise + (size_t)gb0 * FS_ + lane;
    float*       out_b   = out   + (size_t)gb0 * (FS_*T_) + (size_t)lane * T_;

    float2 areg[4];    // role 1: prefetched a-tiles
    float  eps_n[4];   // roles 2,3: next-step noise (both load; kills eps exchange)

    // -------- prologue --------
#pragma unroll
    for (int e = 0; e < 4; e++) {
        float xv = x0[(size_t)(gb0 + e) * FS_ + lane];
        v_sm[wid][e][lane] = xv;
        if (role == 0) out_b[(size_t)e * (FS_*T_)] = xv;
    }
    if (role == 1) {
#pragma unroll
        for (int e = 0; e < 4; e++) {
            float2 v = *reinterpret_cast<const float2*>(a_base + (size_t)e * (FA_*T_));
            a_sg[0][el0 + e][(lane & 1)*2 + 0][lane >> 1] = v.x;
            a_sg[0][el0 + e][(lane & 1)*2 + 1][lane >> 1] = v.y;
        }
#pragma unroll
        for (int e = 0; e < 4; e++)
            areg[e] = *reinterpret_cast<const float2*>(a_base + (size_t)e * (FA_*T_) + 4);
    }
    if (isg) {
#pragma unroll
        for (int e = 0; e < 4; e++) eps_n[e] = nz_base[e * FS_];
    }
    __syncthreads();

    const int bar_id = 1 + grp;           // 128-thread group barrier

#pragma unroll 1
    for (int t = 1; t < T_; t++) {
        const int ai  = t - 1;
        const int tb  = t & 1;
        const int g4  = ai >> 2;
        const int buf = g4 & 1;
        const int sl  = ai & 3;

        // g warps: rotate noise double-buffer; issue next loads early
        float es[4];
        if (isg) {
#pragma unroll
            for (int e = 0; e < 4; e++) es[e] = eps_n[e] * SQRT_DT_;
            if (t < T_ - 1) {
                const float* np = nz_base + (size_t)t * (B_ * FS_);
#pragma unroll
                for (int e = 0; e < 4; e++) eps_n[e] = np[e * FS_];
            }
        }

        // ------- layer 1 half: h[jb+lane] for 4 elements (4 chains) -------
        u64 acc[4];
#pragma unroll
        for (int e = 0; e < 4; e++) acc[e] = 0ull;
#pragma unroll
        for (int e = 0; e < 4; e++) {
            const ulonglong2* ap = reinterpret_cast<const ulonglong2*>(&a_sg[buf][el0+e][sl][0]);
            const ulonglong2* xp = reinterpret_cast<const ulonglong2*>(&v_sm[wid][e][0]);
#pragma unroll
            for (int q = 0; q < 4; q++) {            // s[0:16) = a_t
                ulonglong2 v = ap[q];
                acc[e] = ffma2(v.x, w1h[2*q],   acc[e]);
                acc[e] = ffma2(v.y, w1h[2*q+1], acc[e]);
            }
#pragma unroll
            for (int q = 0; q < 8; q++) {            // s[16:48) = x_t
                ulonglong2 v = xp[q];
                acc[e] = ffma2(v.x, w1h[8+2*q], acc[e]);
                acc[e] = ffma2(v.y, w1h[9+2*q], acc[e]);
            }
        }
        // tanh + stash h-half in private buffer (overwrites x)
#pragma unroll
        for (int e = 0; e < 4; e++) {
            float2 u = unpack2(acc[e]);
            v_sm[wid][e][lane] = tanh_acc(u.x + u.y + b1v);
        }
        __syncwarp();

        // ------- layer 2 partial over own k-half; publish packed -------
#pragma unroll
        for (int e = 0; e < 4; e++) {
            const ulonglong2* hp = reinterpret_cast<const ulonglong2*>(&v_sm[wid][e][0]);
            u64 c = 0ull;
#pragma unroll
            for (int q = 0; q < 8; q++) {
                ulonglong2 v = hp[q];
                c = ffma2(v.x, w2h[2*q],   c);
                c = ffma2(v.y, w2h[2*q+1], c);
            }
            float2 u = unpack2(c);
            float p = u.x + u.y + pbias;
            if (isg) p *= es[e];                      // pre-scale g partials
            reinterpret_cast<float*>(&ex_sm[tb][grp][e][lane])[role] = p;
        }

        // role 1: a-tile staging pre-barrier (fills partner-wait window)
        if (role == 1) {
            if (sl == 2 && g4 + 1 < 128) {
#pragma unroll
                for (int e = 0; e < 4; e++) {
                    a_sg[buf ^ 1][el0 + e][(lane & 1)*2 + 0][lane >> 1] = areg[e].x;
                    a_sg[buf ^ 1][el0 + e][(lane & 1)*2 + 1][lane >> 1] = areg[e].y;
                }
            }
            if (sl == 3 && g4 + 2 < 128) {
                const float* ap = a_base + (size_t)(g4 + 2) * 4;
#pragma unroll
                for (int e = 0; e < 4; e++)
                    areg[e] = *reinterpret_cast<const float2*>(ap + (size_t)e * (FA_*T_));
            }
        }

        asm volatile("bar.sync %0, 128;" :: "r"(bar_id) : "memory");

        // ------- all 4 warps redundantly finalize x (1 LDS.128 each) -------
#pragma unroll
        for (int e = 0; e < 4; e++) {
            float4 P = ex_sm[tb][grp][e][lane];
            float xv = (P.x + P.y) + (P.z + P.w);
            xv = fminf(fmaxf(xv, MIN_V_), MAX_V_);
            v_sm[wid][e][lane] = xv;                  // overwrite h with new x
            if (role == 0) out_b[(size_t)e * (FS_*T_) + t] = xv;
        }
        __syncwarp();
    }
}

extern "C" void kernel_launch(void* const* d_in, const int* in_sizes, int n_in,
                              void* d_out, int out_size) {
    (void)in_sizes; (void)n_in; (void)out_size;
    // metadata order: ts, in_signal, x0, noise, Wf1, bf1, Wf2, bf2, Wg1, bg1, Wg2, bg2
    const float* a_in  = (const float*)d_in[1];
    const float* x0    = (const float*)d_in[2];
    const float* noise = (const float*)d_in[3];
    const float* Wf1   = (const float*)d_in[4];
    const float* bf1   = (const float*)d_in[5];
    const float* Wf2   = (const float*)d_in[6];
    const float* bf2   = (const float*)d_in[7];
    const float* Wg1   = (const float*)d_in[8];
    const float* bg1   = (const float*)d_in[9];
    const float* Wg2   = (const float*)d_in[10];
    const float* bg2   = (const float*)d_in[11];
    float* out = (float*)d_out;

    sde_kernel<<<B_ / 8, 256>>>(a_in, x0, noise,
                                Wf1, bf1, Wf2, bf2,
                                Wg1, bg1, Wg2, bg2,
                                out);
}

// round 10
// speedup vs baseline: 1.4201x; 1.4201x over previous
#include <cuda_runtime.h>

#define B_    2048
#define FS_   32
#define FA_   16
#define T_    512
#define H_    64
#define SQRT_DT_ 0.22360679774997896f
#define MIN_V_  (-5.0f)
#define MAX_V_  (5.0f)

typedef unsigned long long u64;

__device__ __forceinline__ u64 pack2(float lo, float hi) {
    u64 r; asm("mov.b64 %0, {%1, %2};" : "=l"(r) : "f"(lo), "f"(hi)); return r;
}
__device__ __forceinline__ float2 unpack2(u64 v) {
    float2 f; asm("mov.b64 {%0, %1}, %2;" : "=f"(f.x), "=f"(f.y) : "l"(v)); return f;
}
// packed dual fp32 FMA / ADD (sm_100+)
__device__ __forceinline__ u64 ffma2(u64 a, u64 b, u64 c) {
    u64 d; asm("fma.rn.f32x2 %0, %1, %2, %3;" : "=l"(d) : "l"(a), "l"(b), "l"(c)); return d;
}
__device__ __forceinline__ u64 fadd2(u64 a, u64 b) {
    u64 d; asm("add.rn.f32x2 %0, %1, %2;" : "=l"(d) : "l"(a), "l"(b)); return d;
}
// accurate tanh from ex2.approx + rcp.approx (~1e-7 abs err)
__device__ __forceinline__ float tanh_acc(float x) {
    float e, r;
    asm("ex2.approx.f32 %0, %1;" : "=f"(e) : "f"(x * 2.8853900817779268f)); // 2*log2(e)
    asm("rcp.approx.f32 %0, %1;" : "=f"(r) : "f"(e + 1.0f));
    return (e - 1.0f) * r;
}

// R4 topology (256 thr = 4 (f,g) pairs x 4 elements, grid=128, full register
// weights, ONE named barrier/step, redundant finalize) with per-warp stall
// reduction: q-outer/e-inner load interleaving in L1/L2, packed epilogue adds,
// es precompute, g-warp staging / f-warp 2-step-batched STG.64 outputs.
__global__ void __launch_bounds__(256, 1)
sde_kernel(const float* __restrict__ a_in,   // (B, FA, T)
           const float* __restrict__ x0,     // (B, FS)
           const float* __restrict__ noise,  // (T-1, B, FS)
           const float* __restrict__ Wf1, const float* __restrict__ bf1,
           const float* __restrict__ Wf2, const float* __restrict__ bf2,
           const float* __restrict__ Wg1, const float* __restrict__ bg1,
           const float* __restrict__ Wg2, const float* __restrict__ bg2,
           float* __restrict__ out)          // (B, FS, T)
{
    const int tid  = threadIdx.x;
    const int wid  = tid >> 5;
    const int lane = tid & 31;
    const int pair = wid >> 1;            // 0..3
    const bool is_g = (wid & 1) != 0;
    const int el0  = pair * 4;
    const int gb0  = blockIdx.x * 16 + el0;

    __shared__ __align__(16) float v_sm[8][4][64];        // per-warp x/h buffer (8KB)
    __shared__ __align__(16) float a_sg[2][16][4][16];    // a tiles, 4 steps, transposed (8KB)
    __shared__ __align__(16) float ex_sm[2][4][2][4][32]; // {o_f,d} exchange, dbl-buf (8KB)

    const float* W1 = is_g ? Wg1 : Wf1;
    const float* b1 = is_g ? bg1 : bf1;
    const float* W2 = is_g ? Wg2 : Wf2;
    const float* b2 = is_g ? bg2 : bf2;

    // -------- register-resident weights, packed (k, k+1) over k --------
    u64 w1a[24], w1b[24], w2p[32];
#pragma unroll
    for (int kp = 0; kp < 24; kp++) {
        w1a[kp] = pack2(W1[(2*kp)*H_ + lane],      W1[(2*kp+1)*H_ + lane]);
        w1b[kp] = pack2(W1[(2*kp)*H_ + lane + 32], W1[(2*kp+1)*H_ + lane + 32]);
    }
#pragma unroll
    for (int kp = 0; kp < 32; kp++) {
        w2p[kp] = pack2(W2[(2*kp)*FS_ + lane], W2[(2*kp+1)*FS_ + lane]);
    }
    const float bias1a = b1[lane];
    const float bias1b = b1[lane + 32];
    const float bias2  = b2[lane];

    const float* a_base  = a_in  + (size_t)gb0 * (FA_*T_) + (size_t)(lane >> 1) * T_ + (lane & 1) * 2;
    const float* nz_base = noise + (size_t)gb0 * FS_ + lane;
    float*       out_b   = out   + (size_t)gb0 * (FS_*T_) + (size_t)lane * T_;

    float2 areg[4];     // g: prefetched a-tiles (staging moved to g)
    float  eps_n[4];    // g: next-step noise
    float2 hist[4];     // f: 2-step output history per element

    // -------- prologue --------
#pragma unroll
    for (int e = 0; e < 4; e++) {
        float xv = x0[(size_t)(gb0 + e) * FS_ + lane];
        v_sm[wid][e][lane] = xv;
        if (!is_g) hist[e].x = xv;       // t=0 goes into the 2-step batch
    }
    if (is_g) {
#pragma unroll
        for (int e = 0; e < 4; e++) {
            float2 v = *reinterpret_cast<const float2*>(a_base + (size_t)e * (FA_*T_));
            a_sg[0][el0 + e][(lane & 1)*2 + 0][lane >> 1] = v.x;
            a_sg[0][el0 + e][(lane & 1)*2 + 1][lane >> 1] = v.y;
        }
#pragma unroll
        for (int e = 0; e < 4; e++)
            areg[e] = *reinterpret_cast<const float2*>(a_base + (size_t)e * (FA_*T_) + 4);
#pragma unroll
        for (int e = 0; e < 4; e++) eps_n[e] = nz_base[e * FS_];
    }
    __syncthreads();

    const int bar_id = 1 + pair;

#pragma unroll 1
    for (int t = 1; t < T_; t++) {
        const int ai  = t - 1;
        const int tb  = t & 1;
        const int g4  = ai >> 2;
        const int buf = g4 & 1;
        const int sl  = ai & 3;

        // g: es for this step; issue next noise loads early (fire and forget)
        float es[4];
        if (is_g) {
#pragma unroll
            for (int e = 0; e < 4; e++) es[e] = eps_n[e] * SQRT_DT_;
            if (t < T_ - 1) {
                const float* np = nz_base + (size_t)t * (B_ * FS_);
#pragma unroll
                for (int e = 0; e < 4; e++) eps_n[e] = np[e * FS_];
            }
        }

        // ---------------- layer 1 (48 -> 64), q-outer / e-inner ----------------
        u64 aa[4], ab[4];
#pragma unroll
        for (int e = 0; e < 4; e++) { aa[e] = 0ull; ab[e] = 0ull; }

        // a-part: 4 q-groups; each: 4 independent LDS.128 then 16 ffma2
#pragma unroll
        for (int q = 0; q < 4; q++) {
            ulonglong2 v0 = *reinterpret_cast<const ulonglong2*>(&a_sg[buf][el0+0][sl][4*q]);
            ulonglong2 v1 = *reinterpret_cast<const ulonglong2*>(&a_sg[buf][el0+1][sl][4*q]);
            ulonglong2 v2 = *reinterpret_cast<const ulonglong2*>(&a_sg[buf][el0+2][sl][4*q]);
            ulonglong2 v3 = *reinterpret_cast<const ulonglong2*>(&a_sg[buf][el0+3][sl][4*q]);
            const u64 wA0 = w1a[2*q], wA1 = w1a[2*q+1];
            const u64 wB0 = w1b[2*q], wB1 = w1b[2*q+1];
            aa[0] = ffma2(v0.x, wA0, aa[0]); aa[0] = ffma2(v0.y, wA1, aa[0]);
            aa[1] = ffma2(v1.x, wA0, aa[1]); aa[1] = ffma2(v1.y, wA1, aa[1]);
            aa[2] = ffma2(v2.x, wA0, aa[2]); aa[2] = ffma2(v2.y, wA1, aa[2]);
            aa[3] = ffma2(v3.x, wA0, aa[3]); aa[3] = ffma2(v3.y, wA1, aa[3]);
            ab[0] = ffma2(v0.x, wB0, ab[0]); ab[0] = ffma2(v0.y, wB1, ab[0]);
            ab[1] = ffma2(v1.x, wB0, ab[1]); ab[1] = ffma2(v1.y, wB1, ab[1]);
            ab[2] = ffma2(v2.x, wB0, ab[2]); ab[2] = ffma2(v2.y, wB1, ab[2]);
            ab[3] = ffma2(v3.x, wB0, ab[3]); ab[3] = ffma2(v3.y, wB1, ab[3]);
        }
        // x-part: 8 q-groups
#pragma unroll
        for (int q = 0; q < 8; q++) {
            ulonglong2 v0 = *reinterpret_cast<const ulonglong2*>(&v_sm[wid][0][4*q]);
            ulonglong2 v1 = *reinterpret_cast<const ulonglong2*>(&v_sm[wid][1][4*q]);
            ulonglong2 v2 = *reinterpret_cast<const ulonglong2*>(&v_sm[wid][2][4*q]);
            ulonglong2 v3 = *reinterpret_cast<const ulonglong2*>(&v_sm[wid][3][4*q]);
            const u64 wA0 = w1a[8+2*q], wA1 = w1a[9+2*q];
            const u64 wB0 = w1b[8+2*q], wB1 = w1b[9+2*q];
            aa[0] = ffma2(v0.x, wA0, aa[0]); aa[0] = ffma2(v0.y, wA1, aa[0]);
            aa[1] = ffma2(v1.x, wA0, aa[1]); aa[1] = ffma2(v1.y, wA1, aa[1]);
            aa[2] = ffma2(v2.x, wA0, aa[2]); aa[2] = ffma2(v2.y, wA1, aa[2]);
            aa[3] = ffma2(v3.x, wA0, aa[3]); aa[3] = ffma2(v3.y, wA1, aa[3]);
            ab[0] = ffma2(v0.x, wB0, ab[0]); ab[0] = ffma2(v0.y, wB1, ab[0]);
            ab[1] = ffma2(v1.x, wB0, ab[1]); ab[1] = ffma2(v1.y, wB1, ab[1]);
            ab[2] = ffma2(v2.x, wB0, ab[2]); ab[2] = ffma2(v2.y, wB1, ab[2]);
            ab[3] = ffma2(v3.x, wB0, ab[3]); ab[3] = ffma2(v3.y, wB1, ab[3]);
        }
        // tanh + stash h (overwrites x in private buffer)
#pragma unroll
        for (int e = 0; e < 4; e++) {
            float2 u = unpack2(aa[e]);
            float2 v = unpack2(ab[e]);
            v_sm[wid][e][lane]      = tanh_acc(u.x + u.y + bias1a);
            v_sm[wid][e][lane + 32] = tanh_acc(v.x + v.y + bias1b);
        }
        __syncwarp();

        // ---------------- layer 2 (64 -> 32), q-outer / e-inner ----------------
        u64 c0[4], c1[4];
#pragma unroll
        for (int e = 0; e < 4; e++) { c0[e] = 0ull; c1[e] = 0ull; }
#pragma unroll
        for (int q = 0; q < 16; q++) {
            ulonglong2 v0 = *reinterpret_cast<const ulonglong2*>(&v_sm[wid][0][4*q]);
            ulonglong2 v1 = *reinterpret_cast<const ulonglong2*>(&v_sm[wid][1][4*q]);
            ulonglong2 v2 = *reinterpret_cast<const ulonglong2*>(&v_sm[wid][2][4*q]);
            ulonglong2 v3 = *reinterpret_cast<const ulonglong2*>(&v_sm[wid][3][4*q]);
            const u64 w0 = w2p[2*q], w1x = w2p[2*q+1];
            c0[0] = ffma2(v0.x, w0, c0[0]); c1[0] = ffma2(v0.y, w1x, c1[0]);
            c0[1] = ffma2(v1.x, w0, c0[1]); c1[1] = ffma2(v1.y, w1x, c1[1]);
            c0[2] = ffma2(v2.x, w0, c0[2]); c1[2] = ffma2(v2.y, w1x, c1[2]);
            c0[3] = ffma2(v3.x, w0, c0[3]); c1[3] = ffma2(v3.y, w1x, c1[3]);
        }
        float o[4];
#pragma unroll
        for (int e = 0; e < 4; e++) {
            float2 u = unpack2(fadd2(c0[e], c1[e]));
            o[e] = (u.x + u.y) + bias2;
        }

        // publish: f -> o_f (incl. bias), g -> full diffusion term d
        if (!is_g) {
#pragma unroll
            for (int e = 0; e < 4; e++) ex_sm[tb][pair][0][e][lane] = o[e];
        } else {
#pragma unroll
            for (int e = 0; e < 4; e++) ex_sm[tb][pair][1][e][lane] = o[e] * es[e];
        }

        // g: a-tile staging pre-barrier (fills partner-wait window)
        if (is_g) {
            if (sl == 2 && g4 + 1 < 128) {
#pragma unroll
                for (int e = 0; e < 4; e++) {
                    a_sg[buf ^ 1][el0 + e][(lane & 1)*2 + 0][lane >> 1] = areg[e].x;
                    a_sg[buf ^ 1][el0 + e][(lane & 1)*2 + 1][lane >> 1] = areg[e].y;
                }
            }
            if (sl == 3 && g4 + 2 < 128) {
                const float* ap = a_base + (size_t)(g4 + 2) * 4;
#pragma unroll
                for (int e = 0; e < 4; e++)
                    areg[e] = *reinterpret_cast<const float2*>(ap + (size_t)e * (FA_*T_));
            }
        }

        asm volatile("bar.sync %0, 64;" :: "r"(bar_id) : "memory");

        // both warps redundantly finalize x into their own buffer;
        // f batches global stores 2 steps -> STG.64
#pragma unroll
        for (int e = 0; e < 4; e++) {
            float xv = ex_sm[tb][pair][0][e][lane] + ex_sm[tb][pair][1][e][lane];
            xv = fminf(fmaxf(xv, MIN_V_), MAX_V_);
            v_sm[wid][e][lane] = xv;
            if (!is_g) {
                if (tb) {   // t odd: complete (t-1, t) pair and store
                    hist[e].y = xv;
                    *reinterpret_cast<float2*>(out_b + (size_t)e * (FS_*T_) + (t - 1)) = hist[e];
                } else {
                    hist[e].x = xv;
                }
            }
        }
        __syncwarp();
    }
}

extern "C" void kernel_launch(void* const* d_in, const int* in_sizes, int n_in,
                              void* d_out, int out_size) {
    (void)in_sizes; (void)n_in; (void)out_size;
    // metadata order: ts, in_signal, x0, noise, Wf1, bf1, Wf2, bf2, Wg1, bg1, Wg2, bg2
    const float* a_in  = (const float*)d_in[1];
    const float* x0    = (const float*)d_in[2];
    const float* noise = (const float*)d_in[3];
    const float* Wf1   = (const float*)d_in[4];
    const float* bf1   = (const float*)d_in[5];
    const float* Wf2   = (const float*)d_in[6];
    const float* bf2   = (const float*)d_in[7];
    const float* Wg1   = (const float*)d_in[8];
    const float* bg1   = (const float*)d_in[9];
    const float* Wg2   = (const float*)d_in[10];
    const float* bg2   = (const float*)d_in[11];
    float* out = (float*)d_out;

    sde_kernel<<<B_ / 16, 256>>>(a_in, x0, noise,
                                 Wf1, bf1, Wf2, bf2,
                                 Wg1, bg1, Wg2, bg2,
                                 out);
}